// round 1
// baseline (speedup 1.0000x reference)
#include <cuda_runtime.h>

#define BB    64
#define L1S   199
#define LL    200
#define NUMC  1000
#define DD    64
#define MM    50
#define TPB_POS 8

// ---- scratch (static device globals; no allocation) ----
__device__ float g_k[BB*LL*DD];
__device__ float g_w[BB*LL*MM];
__device__ float g_e[BB*LL*DD];
__device__ float g_a[BB*LL*DD];
__device__ float g_read[BB*LL*DD];

// ============================================================
// Kernel A: per-position precompute of k, w(softmax), e, a.
// One block (64 threads) handles TPB_POS positions; Mk^T staged in smem.
// ============================================================
__global__ void precompute_kernel(
    const int*  __restrict__ cseqs,  const int* __restrict__ rseqs,
    const int*  __restrict__ shc,    const int* __restrict__ shr,
    const float* __restrict__ kemb,  const float* __restrict__ vemb,
    const float* __restrict__ Mk,
    const float* __restrict__ We,    const float* __restrict__ be,
    const float* __restrict__ Wa,    const float* __restrict__ ba)
{
    __shared__ float MkT[DD*MM];     // transposed: MkT[i*MM + m] = Mk[m*DD + i]
    __shared__ float ks[DD], vs[DD], lg[MM];
    __shared__ float sm_max, sm_inv;

    const int tid = threadIdx.x;     // 64 threads

    // stage Mk transposed (coalesced global reads)
    #pragma unroll 10
    for (int j = 0; j < MM; j++) {
        float v = Mk[j*DD + tid];    // row j, col tid
        MkT[tid*MM + j] = v;
    }
    __syncthreads();

    const int base = blockIdx.x * TPB_POS;
    for (int p = 0; p < TPB_POS; p++) {
        const int pos = base + p;
        const int b = pos / LL;
        const int t = pos % LL;

        const int q  = (t == 0) ? cseqs[b*L1S] : shc[b*L1S + t - 1];
        const int rr = (t == 0) ? rseqs[b*L1S] : shr[b*L1S + t - 1];
        const int x  = q + NUMC * rr;

        __syncthreads();             // protect ks/vs/lg reuse across iterations
        float kd = kemb[q*DD + tid];
        float vd = vemb[x*DD + tid];
        ks[tid] = kd;
        vs[tid] = vd;
        g_k[pos*DD + tid] = kd;
        __syncthreads();

        // logits (threads 0..49)
        if (tid < MM) {
            float s = 0.f;
            #pragma unroll 16
            for (int i = 0; i < DD; i++)
                s += ks[i] * MkT[i*MM + tid];
            lg[tid] = s;
        }

        // erase / add gates (all 64 threads, coalesced weight loads)
        float ed = be[tid], ad = ba[tid];
        #pragma unroll 8
        for (int i = 0; i < DD; i++) {
            float vi = vs[i];
            ed += vi * We[i*DD + tid];
            ad += vi * Wa[i*DD + tid];
        }
        g_e[pos*DD + tid] = 1.f / (1.f + __expf(-ed));
        g_a[pos*DD + tid] = tanhf(ad);

        __syncthreads();
        if (tid == 0) {
            float mx = lg[0];
            for (int m = 1; m < MM; m++) mx = fmaxf(mx, lg[m]);
            sm_max = mx;
        }
        __syncthreads();
        if (tid < MM) lg[tid] = __expf(lg[tid] - sm_max);
        __syncthreads();
        if (tid == 0) {
            float s = 0.f;
            for (int m = 0; m < MM; m++) s += lg[m];
            sm_inv = 1.f / s;
        }
        __syncthreads();
        if (tid < MM) g_w[pos*MM + tid] = lg[tid] * sm_inv;
    }
}

// ============================================================
// Kernel B: sequential memory scan. One block per batch element.
// 256 threads; thread (g = tid>>6, d = tid&63) owns Mv[m,d] for
// m = g, g+4, g+8, ... (12-13 rows) entirely in registers.
// Whole sequence of w/e/a staged in dynamic smem once.
// ============================================================
__global__ void scan_kernel(const float* __restrict__ Mv0)
{
    extern __shared__ float smem[];
    float* sw   = smem;                    // LL*MM  = 10000
    float* se   = sw + LL*MM;              // LL*DD  = 12800
    float* sa   = se + LL*DD;              // LL*DD  = 12800
    float* sred = sa + LL*DD;              // 2*256  = 512 (parity buffers)

    const int b   = blockIdx.x;
    const int tid = threadIdx.x;           // 256

    // cooperative staging (float4 vectorized, coalesced)
    {
        const float4* gw4 = (const float4*)(g_w + b*LL*MM);
        float4* sw4 = (float4*)sw;
        for (int i = tid; i < LL*MM/4; i += 256) sw4[i] = gw4[i];
        const float4* ge4 = (const float4*)(g_e + b*LL*DD);
        float4* se4 = (float4*)se;
        for (int i = tid; i < LL*DD/4; i += 256) se4[i] = ge4[i];
        const float4* ga4 = (const float4*)(g_a + b*LL*DD);
        float4* sa4 = (float4*)sa;
        for (int i = tid; i < LL*DD/4; i += 256) sa4[i] = ga4[i];
    }

    const int g = tid >> 6;
    const int d = tid & 63;

    float mv[13];
    #pragma unroll
    for (int mi = 0; mi < 13; mi++) {
        int m = g + 4*mi;
        mv[mi] = (m < MM) ? Mv0[m*DD + d] : 0.f;
    }
    __syncthreads();

    float* outr = g_read + b*LL*DD;

    for (int t = 0; t < LL; t++) {
        const float e = se[t*DD + d];
        const float a = sa[t*DD + d];
        const float* wt = sw + t*MM;
        float pr = 0.f;
        #pragma unroll
        for (int mi = 0; mi < 13; mi++) {
            int m = g + 4*mi;
            if (m < MM) {
                float wm = wt[m];           // warp-uniform -> smem broadcast
                pr += wm * mv[mi];          // read BEFORE update
                mv[mi] += wm * (a - e*mv[mi]);  // Mv*(1-w e) + w a
            }
        }
        const int par = (t & 1) * 256;
        sred[par + tid] = pr;
        __syncthreads();
        if (g == 0) {
            float r = sred[par + d] + sred[par + 64 + d]
                    + sred[par + 128 + d] + sred[par + 192 + d];
            outr[t*DD + d] = r;
        }
        // parity double-buffer: next iter writes the other bank, so the
        // single barrier above is sufficient per step.
    }
}

// ============================================================
// Kernel C: output MLP per position. f = tanh([read,k]@Wf+bf),
// p = sigmoid(f@Wp+bp). One 64-thread block per position.
// ============================================================
__global__ void output_kernel(
    const float* __restrict__ Wf, const float* __restrict__ bf,
    const float* __restrict__ Wp, const float* __restrict__ bp,
    float* __restrict__ out)
{
    __shared__ float info[2*DD];
    __shared__ float sred[2];

    const int pos = blockIdx.x;
    const int tid = threadIdx.x;   // 64

    info[tid]      = g_read[pos*DD + tid];
    info[DD + tid] = g_k[pos*DD + tid];
    __syncthreads();

    float f = bf[tid];
    #pragma unroll 8
    for (int i = 0; i < 2*DD; i++)
        f += info[i] * Wf[i*DD + tid];   // coalesced weight loads
    f = tanhf(f);

    float p = f * Wp[tid];
    #pragma unroll
    for (int o = 16; o > 0; o >>= 1)
        p += __shfl_down_sync(0xffffffffu, p, o);
    if ((tid & 31) == 0) sred[tid >> 5] = p;
    __syncthreads();
    if (tid == 0) {
        float s = sred[0] + sred[1] + bp[0];
        out[pos] = 1.f / (1.f + __expf(-s));
    }
}

// ============================================================
extern "C" void kernel_launch(void* const* d_in, const int* in_sizes, int n_in,
                              void* d_out, int out_size)
{
    const int*   cseqs = (const int*)  d_in[0];
    const int*   rseqs = (const int*)  d_in[1];
    const int*   shc   = (const int*)  d_in[2];
    const int*   shr   = (const int*)  d_in[3];
    const float* kemb  = (const float*)d_in[4];
    const float* vemb  = (const float*)d_in[5];
    const float* Mk    = (const float*)d_in[6];
    const float* Mv0   = (const float*)d_in[7];
    const float* Wf    = (const float*)d_in[8];
    const float* bf    = (const float*)d_in[9];
    const float* We    = (const float*)d_in[10];
    const float* be    = (const float*)d_in[11];
    const float* Wa    = (const float*)d_in[12];
    const float* ba    = (const float*)d_in[13];
    const float* Wp    = (const float*)d_in[14];
    const float* bp    = (const float*)d_in[15];
    float* out = (float*)d_out;

    precompute_kernel<<<BB*LL/TPB_POS, 64>>>(cseqs, rseqs, shc, shr,
                                             kemb, vemb, Mk, We, be, Wa, ba);

    size_t smem = (size_t)(LL*MM + 2*LL*DD + 512) * sizeof(float); // 144,448 B
    cudaFuncSetAttribute(scan_kernel,
                         cudaFuncAttributeMaxDynamicSharedMemorySize, (int)smem);
    scan_kernel<<<BB, 256, smem>>>(Mv0);

    output_kernel<<<BB*LL, 64>>>(Wf, bf, Wp, bp, out);
}

// round 2
// speedup vs baseline: 1.7658x; 1.7658x over previous
#include <cuda_runtime.h>

#define BB    64
#define L1S   199
#define LL    200
#define NUMC  1000
#define DD    64
#define MM    50
#define DR    32          // d-range per scan block (DSPLIT=2)
#define NG    8           // thread groups in scan block (256/DR)
#define MIR   7           // ceil(MM/NG) m-rows per thread

// ---- scratch (static device globals; no allocation) ----
__device__ float g_Wall[NUMC*MM];      // softmax(kemb @ Mk^T)        [1000,50]
__device__ float g_Eall[2*NUMC*DD];    // sigmoid(vemb @ We + be)     [2000,64]
__device__ float g_Aall[2*NUMC*DD];    // tanh(vemb @ Wa + ba)        [2000,64]
__device__ float g_Kf  [NUMC*DD];      // kemb @ Wf[D:2D] + bf        [1000,64]
__device__ float g_read[BB*LL*DD];     // weighted read               [B,L,64]

// ============================================================
// Kernel V: vocabulary-indexed precompute. grid=2000, block=64.
// Block v: E_all/A_all row v; if v<1000 also W_all + Kf rows.
// ============================================================
__global__ void vocab_kernel(
    const float* __restrict__ kemb,  const float* __restrict__ vemb,
    const float* __restrict__ Mk,
    const float* __restrict__ We,    const float* __restrict__ be,
    const float* __restrict__ Wa,    const float* __restrict__ ba,
    const float* __restrict__ Wf,    const float* __restrict__ bf)
{
    __shared__ float vs[DD];
    __shared__ float ks[DD];
    __shared__ float MkT[DD*MM];      // MkT[i*MM+m] = Mk[m*DD+i]
    __shared__ float lg[MM];
    __shared__ float s01[2];

    const int row = blockIdx.x;       // 0..1999
    const int d   = threadIdx.x;      // 0..63

    vs[d] = vemb[row*DD + d];
    if (row < NUMC) {
        ks[d] = kemb[row*DD + d];
        // stage Mk transposed (coalesced reads)
        #pragma unroll
        for (int j = d; j < MM*DD; j += DD) {
            int m = j / DD, i = j % DD;
            MkT[i*MM + m] = Mk[j];
        }
    }
    __syncthreads();

    // erase / add gates for row (x index)
    float ed = be[d], ad = ba[d];
    #pragma unroll 8
    for (int i = 0; i < DD; i++) {
        float vi = vs[i];
        ed = fmaf(vi, We[i*DD + d], ed);
        ad = fmaf(vi, Wa[i*DD + d], ad);
    }
    g_Eall[row*DD + d] = 1.f / (1.f + __expf(-ed));
    g_Aall[row*DD + d] = tanhf(ad);

    if (row < NUMC) {
        // Kf = kemb @ Wf[D:2D] + bf
        float kf = bf[d];
        #pragma unroll 8
        for (int i = 0; i < DD; i++)
            kf = fmaf(ks[i], Wf[(DD + i)*DD + d], kf);
        g_Kf[row*DD + d] = kf;

        // W_all = softmax(kemb @ Mk^T)
        if (d < MM) {
            float s = 0.f;
            #pragma unroll 16
            for (int i = 0; i < DD; i++)
                s = fmaf(ks[i], MkT[i*MM + d], s);
            lg[d] = s;
        }
        __syncthreads();
        if (d == 0) {
            float mx = lg[0];
            for (int m = 1; m < MM; m++) mx = fmaxf(mx, lg[m]);
            s01[0] = mx;
        }
        __syncthreads();
        if (d < MM) lg[d] = __expf(lg[d] - s01[0]);
        __syncthreads();
        if (d == 0) {
            float s = 0.f;
            for (int m = 0; m < MM; m++) s += lg[m];
            s01[1] = 1.f / s;
        }
        __syncthreads();
        if (d < MM) g_Wall[row*MM + d] = lg[d] * s01[1];
    }
}

// ============================================================
// Kernel S: sequential memory scan, d-split by 2.
// grid = 128 (b = blk>>1, half = blk&1), block = 256.
// Thread (g = tid>>5, dl = tid&31) owns Mv[m, dbase+dl] for
// m = g, g+8, ..., in registers (7 rows).
// ============================================================
__global__ void scan_kernel(
    const int*  __restrict__ cseqs,  const int* __restrict__ rseqs,
    const int*  __restrict__ shc,    const int* __restrict__ shr,
    const float* __restrict__ Mv0)
{
    extern __shared__ float smem[];
    float* sw   = smem;                    // LL*MM  = 10000
    float* se   = sw + LL*MM;              // LL*DR  = 6400
    float* sa   = se + LL*DR;              // LL*DR  = 6400
    float* sred = sa + LL*DR;              // 2*256  = 512 (parity)
    int*   sq   = (int*)(sred + 512);      // LL
    int*   sx   = sq + LL;                 // LL

    const int b     = blockIdx.x >> 1;
    const int dbase = (blockIdx.x & 1) * DR;
    const int tid   = threadIdx.x;

    // indices for this batch
    if (tid < LL) {
        int t = tid;
        int q  = (t == 0) ? cseqs[b*L1S] : shc[b*L1S + t - 1];
        int rr = (t == 0) ? rseqs[b*L1S] : shr[b*L1S + t - 1];
        sq[t] = q;
        sx[t] = q + NUMC * rr;
    }
    __syncthreads();

    // gather-stage w / e / a rows from vocab tables (L2-resident)
    for (int j = tid; j < LL*MM; j += 256) {
        int t = j / MM, m = j - t*MM;
        sw[j] = g_Wall[sq[t]*MM + m];
    }
    for (int j = tid; j < LL*DR; j += 256) {
        int t = j >> 5, dl = j & (DR-1);
        int off = sx[t]*DD + dbase + dl;
        se[j] = g_Eall[off];
        sa[j] = g_Aall[off];
    }

    const int g  = tid >> 5;
    const int dl = tid & (DR-1);

    float mv[MIR];
    #pragma unroll
    for (int mi = 0; mi < MIR; mi++) {
        int m = g + NG*mi;
        mv[mi] = (m < MM) ? Mv0[m*DD + dbase + dl] : 0.f;
    }
    __syncthreads();

    float* outr = g_read + b*LL*DD + dbase;

    for (int t = 0; t < LL; t++) {
        const float e = se[t*DR + dl];
        const float a = sa[t*DR + dl];
        const float* wt = sw + t*MM;
        float pr = 0.f;
        #pragma unroll
        for (int mi = 0; mi < MIR; mi++) {
            int m = g + NG*mi;
            if (m < MM) {
                float wm = wt[m];                 // smem broadcast within group
                pr = fmaf(wm, mv[mi], pr);        // read BEFORE update
                mv[mi] = fmaf(wm, a - e*mv[mi], mv[mi]);
            }
        }
        const int par = (t & 1) * 256;
        sred[par + tid] = pr;
        __syncthreads();
        if (g == 0) {
            float r = sred[par + dl]       + sred[par +  32 + dl]
                    + sred[par +  64 + dl] + sred[par +  96 + dl]
                    + sred[par + 128 + dl] + sred[par + 160 + dl]
                    + sred[par + 192 + dl] + sred[par + 224 + dl];
            outr[t*DD + dl] = r;
        }
        // parity double-buffer -> single barrier per step suffices
    }
}

// ============================================================
// Kernel C: output MLP. f = tanh(read@Wf_top + Kf[q]),
// p = sigmoid(f@Wp + bp). One 64-thread block per position.
// ============================================================
__global__ void output_kernel(
    const int*  __restrict__ cseqs, const int* __restrict__ shc,
    const float* __restrict__ Wf,   const float* __restrict__ Wp,
    const float* __restrict__ bp,   float* __restrict__ out)
{
    __shared__ float rs[DD];
    __shared__ float sred2[2];

    const int pos = blockIdx.x;
    const int tid = threadIdx.x;   // 64
    const int b = pos / LL;
    const int t = pos - b*LL;
    const int q = (t == 0) ? cseqs[b*L1S] : shc[b*L1S + t - 1];

    rs[tid] = g_read[pos*DD + tid];
    __syncthreads();

    float f = g_Kf[q*DD + tid];
    #pragma unroll 8
    for (int i = 0; i < DD; i++)
        f = fmaf(rs[i], Wf[i*DD + tid], f);   // coalesced weight loads
    f = tanhf(f);

    float p = f * Wp[tid];
    #pragma unroll
    for (int o = 16; o > 0; o >>= 1)
        p += __shfl_down_sync(0xffffffffu, p, o);
    if ((tid & 31) == 0) sred2[tid >> 5] = p;
    __syncthreads();
    if (tid == 0)
        out[pos] = 1.f / (1.f + __expf(-(sred2[0] + sred2[1] + bp[0])));
}

// ============================================================
extern "C" void kernel_launch(void* const* d_in, const int* in_sizes, int n_in,
                              void* d_out, int out_size)
{
    const int*   cseqs = (const int*)  d_in[0];
    const int*   rseqs = (const int*)  d_in[1];
    const int*   shc   = (const int*)  d_in[2];
    const int*   shr   = (const int*)  d_in[3];
    const float* kemb  = (const float*)d_in[4];
    const float* vemb  = (const float*)d_in[5];
    const float* Mk    = (const float*)d_in[6];
    const float* Mv0   = (const float*)d_in[7];
    const float* Wf    = (const float*)d_in[8];
    const float* bf    = (const float*)d_in[9];
    const float* We    = (const float*)d_in[10];
    const float* be    = (const float*)d_in[11];
    const float* Wa    = (const float*)d_in[12];
    const float* ba    = (const float*)d_in[13];
    const float* Wp    = (const float*)d_in[14];
    const float* bp    = (const float*)d_in[15];
    float* out = (float*)d_out;

    vocab_kernel<<<2*NUMC, 64>>>(kemb, vemb, Mk, We, be, Wa, ba, Wf, bf);

    size_t smem = (size_t)(LL*MM + 2*LL*DR + 512 + 2*LL/* ints as floats */) * sizeof(float);
    cudaFuncSetAttribute(scan_kernel,
                         cudaFuncAttributeMaxDynamicSharedMemorySize, (int)smem);
    scan_kernel<<<BB*2, 256, smem>>>(cseqs, rseqs, shc, shr, Mv0);

    output_kernel<<<BB*LL, 64>>>(cseqs, shc, Wf, Wp, bp, out);
}

// round 3
// speedup vs baseline: 2.1836x; 1.2366x over previous
#include <cuda_runtime.h>

#define BB    64
#define L1S   199
#define LL    200
#define NUMC  1000
#define DD    64
#define MM    50
#define DR    32          // d-range per scan block (d-split = 2)
#define NG    8           // m-groups per d (one warp holds 8 g x 4 d)

// ---- scratch (static device globals; no allocation) ----
__device__ float g_Wall[NUMC*MM];      // softmax(kemb @ Mk^T)        [1000,50]
__device__ float g_Eall[2*NUMC*DD];    // sigmoid(vemb @ We + be)     [2000,64]
__device__ float g_Aall[2*NUMC*DD];    // tanh(vemb @ Wa + ba)        [2000,64]
__device__ float g_Kf  [NUMC*DD];      // kemb @ Wf[D:2D] + bf        [1000,64]
__device__ float g_read[BB*LL*DD];     // weighted read               [B,L,64]

// ============================================================
// Kernel V: vocab precompute, 4 rows / 256-thread block. grid=500.
// Blocks 0..249 also compute W_all (softmax) and Kf rows.
// ============================================================
__global__ __launch_bounds__(256) void vocab_kernel(
    const float* __restrict__ kemb,  const float* __restrict__ vemb,
    const float* __restrict__ Mk,
    const float* __restrict__ We,    const float* __restrict__ be,
    const float* __restrict__ Wa,    const float* __restrict__ ba,
    const float* __restrict__ Wf,    const float* __restrict__ bf)
{
    __shared__ float vs[4][DD];
    __shared__ float ks[4][DD];
    __shared__ float MkT[DD*MM];      // MkT[i*MM+m] = Mk[m*DD+i]
    __shared__ float part[4][2];

    const int tid = threadIdx.x;
    const int sr  = tid >> 6;         // 0..3 sub-row
    const int d   = tid & 63;
    const int row = blockIdx.x*4 + sr;
    const bool kblk = (blockIdx.x < NUMC/4);   // uniform per block

    vs[sr][d] = vemb[row*DD + d];
    if (kblk) {
        ks[sr][d] = kemb[row*DD + d];
        #pragma unroll
        for (int j = tid; j < MM*DD; j += 256) {
            int m = j >> 6, i = j & 63;
            MkT[i*MM + m] = Mk[j];
        }
    }
    __syncthreads();

    // erase / add gates (x-indexed rows)
    float ed = be[d], ad = ba[d];
    #pragma unroll 8
    for (int i = 0; i < DD; i++) {
        float vi = vs[sr][i];
        ed = fmaf(vi, We[i*DD + d], ed);
        ad = fmaf(vi, Wa[i*DD + d], ad);
    }
    g_Eall[row*DD + d] = 1.f / (1.f + __expf(-ed));
    g_Aall[row*DD + d] = tanhf(ad);

    if (kblk) {
        // Kf = kemb @ Wf[D:2D] + bf
        float kf = bf[d];
        #pragma unroll 8
        for (int i = 0; i < DD; i++)
            kf = fmaf(ks[sr][i], Wf[(DD + i)*DD + d], kf);
        g_Kf[row*DD + d] = kf;

        // W_all = softmax(kemb @ Mk^T)  (logits tiny -> no max shift)
        float lgv = 0.f;
        if (d < MM) {
            float s = 0.f;
            #pragma unroll 16
            for (int i = 0; i < DD; i++)
                s = fmaf(ks[sr][i], MkT[i*MM + d], s);
            lgv = __expf(s);
        }
        float ps = lgv;
        #pragma unroll
        for (int o = 16; o > 0; o >>= 1)
            ps += __shfl_xor_sync(0xffffffffu, ps, o);
        if ((d & 31) == 0) part[sr][d >> 5] = ps;
        __syncthreads();
        if (d < MM)
            g_Wall[row*MM + d] = lgv / (part[sr][0] + part[sr][1]);
    }
}

// ============================================================
// Kernel S: sequential memory scan, barrier-free inner loop.
// grid = 128 (b = blk>>1, d-half = blk&1), block = 256.
// tid = dl*8 + g : warp holds 4 d-lanes x 8 m-groups, so the
// read-reduction over g is 3 shfl_xor (no __syncthreads).
// Thread (g, dl) owns Mv[m, dbase+dl] for m = g+8*mi (registers).
// ============================================================
__global__ __launch_bounds__(256) void scan_kernel(
    const int*  __restrict__ cseqs,  const int* __restrict__ rseqs,
    const int*  __restrict__ shc,    const int* __restrict__ shr,
    const float* __restrict__ Mv0)
{
    extern __shared__ float smem[];
    float* sw = smem;                    // LL*MM = 10000
    float* se = sw + LL*MM;              // LL*DR = 6400
    float* sa = se + LL*DR;              // LL*DR = 6400
    int*   sq = (int*)(sa + LL*DR);      // LL
    int*   sx = sq + LL;                 // LL

    const int b     = blockIdx.x >> 1;
    const int dbase = (blockIdx.x & 1) * DR;
    const int tid   = threadIdx.x;

    if (tid < LL) {
        int t = tid;
        int q  = (t == 0) ? cseqs[b*L1S] : shc[b*L1S + t - 1];
        int rr = (t == 0) ? rseqs[b*L1S] : shr[b*L1S + t - 1];
        sq[t] = q;
        sx[t] = q + NUMC * rr;
    }
    __syncthreads();

    for (int j = tid; j < LL*MM; j += 256) {
        int t = j / MM, m = j - t*MM;
        sw[j] = g_Wall[sq[t]*MM + m];
    }
    for (int j = tid; j < LL*DR; j += 256) {
        int t = j >> 5, dl = j & (DR-1);
        int off = sx[t]*DD + dbase + dl;
        se[j] = g_Eall[off];
        sa[j] = g_Aall[off];
    }

    const int g  = tid & 7;          // low 3 bits of lane -> shfl-reducible
    const int dl = tid >> 3;         // 0..31

    float mv[7];
    #pragma unroll
    for (int mi = 0; mi < 6; mi++)
        mv[mi] = Mv0[(g + NG*mi)*DD + dbase + dl];
    mv[6] = (g < 2) ? Mv0[(g + 48)*DD + dbase + dl] : 0.f;
    __syncthreads();

    float* outr = g_read + b*LL*DD + dbase + dl;

    for (int t = 0; t < LL; t++) {
        const float e  = se[t*DR + dl];
        const float a  = sa[t*DR + dl];
        const float* wt = sw + t*MM;
        float pr0 = 0.f, pr1 = 0.f;
        #pragma unroll
        for (int mi = 0; mi < 6; mi++) {
            float wm = wt[g + NG*mi];
            if (mi & 1) pr1 = fmaf(wm, mv[mi], pr1);
            else        pr0 = fmaf(wm, mv[mi], pr0);
            mv[mi] = fmaf(wm, fmaf(-e, mv[mi], a), mv[mi]);
        }
        if (g < 2) {
            float wm = wt[g + 48];
            pr1 = fmaf(wm, mv[6], pr1);
            mv[6] = fmaf(wm, fmaf(-e, mv[6], a), mv[6]);
        }
        float pr = pr0 + pr1;
        pr += __shfl_xor_sync(0xffffffffu, pr, 1);
        pr += __shfl_xor_sync(0xffffffffu, pr, 2);
        pr += __shfl_xor_sync(0xffffffffu, pr, 4);
        if (g == 0) outr[t*DD] = pr;
    }
}

// ============================================================
// Kernel C: output MLP, 16 positions / block, 4 per thread.
// f = tanh(read @ Wf_top + Kf[q]);  p = sigmoid(f . Wp + bp).
// grid = 800, block = 256 (64 d x 4 position-groups).
// ============================================================
__global__ __launch_bounds__(256) void output_kernel(
    const int*  __restrict__ cseqs, const int* __restrict__ shc,
    const float* __restrict__ Wf,   const float* __restrict__ Wp,
    const float* __restrict__ bp,   float* __restrict__ out)
{
    __shared__ float sW[DD*DD];        // Wf top half (read-part)
    __shared__ float rs[16][DD];
    __shared__ float spart[16][2];

    const int tid  = threadIdx.x;
    const int d    = tid & 63;
    const int pg   = tid >> 6;         // 0..3, owns positions pg*4..pg*4+3
    const int pbase = blockIdx.x * 16;

    #pragma unroll
    for (int j = tid; j < DD*DD; j += 256)
        sW[j] = Wf[j];
    #pragma unroll
    for (int j = tid; j < 16*DD; j += 256)
        rs[j >> 6][j & 63] = g_read[pbase*DD + j];
    __syncthreads();

    // init accumulators with Kf[q_pos][d]
    float acc[4];
    #pragma unroll
    for (int jj = 0; jj < 4; jj++) {
        int pos = pbase + pg*4 + jj;
        int bb = pos / LL, t = pos - bb*LL;
        int q = (t == 0) ? cseqs[bb*L1S] : shc[bb*L1S + t - 1];
        acc[jj] = g_Kf[q*DD + d];
    }

    #pragma unroll 4
    for (int i = 0; i < DD; i++) {
        float wv = sW[i*DD + d];
        acc[0] = fmaf(rs[pg*4 + 0][i], wv, acc[0]);
        acc[1] = fmaf(rs[pg*4 + 1][i], wv, acc[1]);
        acc[2] = fmaf(rs[pg*4 + 2][i], wv, acc[2]);
        acc[3] = fmaf(rs[pg*4 + 3][i], wv, acc[3]);
    }

    const float wp = Wp[d];
    #pragma unroll
    for (int jj = 0; jj < 4; jj++) {
        float p = tanhf(acc[jj]) * wp;
        #pragma unroll
        for (int o = 16; o > 0; o >>= 1)
            p += __shfl_xor_sync(0xffffffffu, p, o);
        if ((d & 31) == 0) spart[pg*4 + jj][d >> 5] = p;
    }
    __syncthreads();
    if (tid < 16) {
        float s = spart[tid][0] + spart[tid][1] + bp[0];
        out[pbase + tid] = 1.f / (1.f + __expf(-s));
    }
}

// ============================================================
extern "C" void kernel_launch(void* const* d_in, const int* in_sizes, int n_in,
                              void* d_out, int out_size)
{
    const int*   cseqs = (const int*)  d_in[0];
    const int*   rseqs = (const int*)  d_in[1];
    const int*   shc   = (const int*)  d_in[2];
    const int*   shr   = (const int*)  d_in[3];
    const float* kemb  = (const float*)d_in[4];
    const float* vemb  = (const float*)d_in[5];
    const float* Mk    = (const float*)d_in[6];
    const float* Mv0   = (const float*)d_in[7];
    const float* Wf    = (const float*)d_in[8];
    const float* bf    = (const float*)d_in[9];
    const float* We    = (const float*)d_in[10];
    const float* be    = (const float*)d_in[11];
    const float* Wa    = (const float*)d_in[12];
    const float* ba    = (const float*)d_in[13];
    const float* Wp    = (const float*)d_in[14];
    const float* bp    = (const float*)d_in[15];
    float* out = (float*)d_out;

    vocab_kernel<<<2*NUMC/4, 256>>>(kemb, vemb, Mk, We, be, Wa, ba, Wf, bf);

    size_t smem = (size_t)(LL*MM + 2*LL*DR) * sizeof(float) + 2*LL*sizeof(int);
    cudaFuncSetAttribute(scan_kernel,
                         cudaFuncAttributeMaxDynamicSharedMemorySize, (int)smem);
    scan_kernel<<<BB*2, 256, smem>>>(cseqs, rseqs, shc, shr, Mv0);

    output_kernel<<<BB*LL/16, 256>>>(cseqs, shc, Wf, Wp, bp, out);
}

// round 4
// speedup vs baseline: 2.3817x; 1.0907x over previous
#include <cuda_runtime.h>

#define BB    64
#define L1S   199
#define LL    200
#define NUMC  1000
#define DD    64
#define MM    50
#define DR    32          // d-range per scan block (d-split = 2)
#define NG    8           // m-groups per d

// ---- scratch (static device globals; no allocation) ----
__device__ float g_Wall[NUMC*MM];      // softmax(kemb @ Mk^T)        [1000,50]
__device__ float g_Eall[2*NUMC*DD];    // sigmoid(vemb @ We + be)     [2000,64]
__device__ float g_Aall[2*NUMC*DD];    // tanh(vemb @ Wa + ba)        [2000,64]
__device__ float g_Kf  [NUMC*DD];      // kemb @ Wf[D:2D] + bf        [1000,64]
__device__ float g_read[BB*LL*DD];     // weighted read               [B,L,64]

// ============================================================
// Kernel V: vocab precompute. grid=125, block=256.
// Each block stages We/Wa/Wf_bot/Mk^T in smem ONCE, then computes
// 16 x-rows (E/A) and 8 k-rows (W softmax + Kf) from smem.
// ============================================================
__global__ __launch_bounds__(256) void vocab_kernel(
    const float* __restrict__ kemb,  const float* __restrict__ vemb,
    const float* __restrict__ Mk,
    const float* __restrict__ We,    const float* __restrict__ be,
    const float* __restrict__ Wa,    const float* __restrict__ ba,
    const float* __restrict__ Wf,    const float* __restrict__ bf)
{
    extern __shared__ float sm[];
    float* sWe  = sm;                 // 4096
    float* sWa  = sWe + DD*DD;        // 4096
    float* sWf  = sWa + DD*DD;        // 4096 (bottom half of Wf)
    float* sMkT = sWf + DD*DD;        // DD*MM = 3200, MkT[i*MM+m]=Mk[m*DD+i]
    float* vs   = sMkT + DD*MM;       // 16*64
    float* ks   = vs + 16*DD;         // 8*64
    float* part = ks + 8*DD;          // 4 pg * 2 rows * 2 warp-halves

    const int tid   = threadIdx.x;
    const int d     = tid & 63;
    const int pg    = tid >> 6;       // 0..3
    const int xbase = blockIdx.x * 16;
    const int kbase = blockIdx.x * 8;

    // ---- stage weights + embeddings (coalesced) ----
    #pragma unroll
    for (int j = tid; j < DD*DD; j += 256) {
        sWe[j] = We[j];
        sWa[j] = Wa[j];
        sWf[j] = Wf[DD*DD + j];       // rows D..2D-1
    }
    #pragma unroll
    for (int j = tid; j < MM*DD; j += 256) {
        int m = j >> 6, i = j & 63;
        sMkT[i*MM + m] = Mk[j];
    }
    #pragma unroll
    for (int j = tid; j < 16*DD; j += 256)
        vs[j] = vemb[xbase*DD + j];
    #pragma unroll
    for (int j = tid; j < 8*DD; j += 256)
        ks[j] = kemb[kbase*DD + j];
    __syncthreads();

    // ---- 16 x-rows: E/A gates (4 rows per pg, register-blocked) ----
    {
        const float bev = be[d], bav = ba[d];
        float ed[4] = {bev, bev, bev, bev};
        float ad[4] = {bav, bav, bav, bav};
        const float* v0 = vs + (pg*4 + 0)*DD;
        const float* v1 = vs + (pg*4 + 1)*DD;
        const float* v2 = vs + (pg*4 + 2)*DD;
        const float* v3 = vs + (pg*4 + 3)*DD;
        #pragma unroll 8
        for (int i = 0; i < DD; i++) {
            const float we = sWe[i*DD + d];
            const float wa = sWa[i*DD + d];
            const float a0 = v0[i], a1 = v1[i], a2 = v2[i], a3 = v3[i];
            ed[0] = fmaf(a0, we, ed[0]);  ad[0] = fmaf(a0, wa, ad[0]);
            ed[1] = fmaf(a1, we, ed[1]);  ad[1] = fmaf(a1, wa, ad[1]);
            ed[2] = fmaf(a2, we, ed[2]);  ad[2] = fmaf(a2, wa, ad[2]);
            ed[3] = fmaf(a3, we, ed[3]);  ad[3] = fmaf(a3, wa, ad[3]);
        }
        #pragma unroll
        for (int jj = 0; jj < 4; jj++) {
            int row = xbase + pg*4 + jj;
            g_Eall[row*DD + d] = 1.f / (1.f + __expf(-ed[jj]));
            g_Aall[row*DD + d] = tanhf(ad[jj]);
        }
    }

    // ---- 8 k-rows: Kf + softmax weights (2 rows per pg) ----
    {
        const float bfv = bf[d];
        float kf[2] = {bfv, bfv};
        float lg[2] = {0.f, 0.f};
        const int md = (d < MM) ? d : 0;      // keep smem idx in-bounds
        const float* k0 = ks + (pg*2 + 0)*DD;
        const float* k1 = ks + (pg*2 + 1)*DD;
        #pragma unroll 8
        for (int i = 0; i < DD; i++) {
            const float wf = sWf[i*DD + d];
            const float mk = sMkT[i*MM + md];
            const float a0 = k0[i], a1 = k1[i];
            kf[0] = fmaf(a0, wf, kf[0]);  lg[0] = fmaf(a0, mk, lg[0]);
            kf[1] = fmaf(a1, wf, kf[1]);  lg[1] = fmaf(a1, mk, lg[1]);
        }
        float lgv[2];
        #pragma unroll
        for (int jj = 0; jj < 2; jj++) {
            g_Kf[(kbase + pg*2 + jj)*DD + d] = kf[jj];
            lgv[jj] = (d < MM) ? __expf(lg[jj]) : 0.f;
            float ps = lgv[jj];
            #pragma unroll
            for (int o = 16; o > 0; o >>= 1)
                ps += __shfl_xor_sync(0xffffffffu, ps, o);
            if ((d & 31) == 0) part[pg*4 + jj*2 + (d >> 5)] = ps;
        }
        __syncthreads();
        #pragma unroll
        for (int jj = 0; jj < 2; jj++) {
            if (d < MM) {
                float s = part[pg*4 + jj*2] + part[pg*4 + jj*2 + 1];
                g_Wall[(kbase + pg*2 + jj)*MM + d] = lgv[jj] / s;
            }
        }
    }
}

// ============================================================
// Kernel S: sequential memory scan, barrier-free inner loop.
// grid = 128 (b = blk>>1, d-half = blk&1), block = 256.
// tid = dl*8 + g : warp holds 4 d-lanes x 8 m-groups -> the
// read-reduction over g is 3 shfl_xor (no __syncthreads).
// ============================================================
__global__ __launch_bounds__(256) void scan_kernel(
    const int*  __restrict__ cseqs,  const int* __restrict__ rseqs,
    const int*  __restrict__ shc,    const int* __restrict__ shr,
    const float* __restrict__ Mv0)
{
    extern __shared__ float smem[];
    float* sw = smem;                    // LL*MM = 10000
    float* se = sw + LL*MM;              // LL*DR = 6400
    float* sa = se + LL*DR;              // LL*DR = 6400
    int*   sq = (int*)(sa + LL*DR);      // LL
    int*   sx = sq + LL;                 // LL

    const int b     = blockIdx.x >> 1;
    const int dbase = (blockIdx.x & 1) * DR;
    const int tid   = threadIdx.x;

    if (tid < LL) {
        int t = tid;
        int q  = (t == 0) ? cseqs[b*L1S] : shc[b*L1S + t - 1];
        int rr = (t == 0) ? rseqs[b*L1S] : shr[b*L1S + t - 1];
        sq[t] = q;
        sx[t] = q + NUMC * rr;
    }
    __syncthreads();

    for (int j = tid; j < LL*MM; j += 256) {
        int t = j / MM, m = j - t*MM;
        sw[j] = g_Wall[sq[t]*MM + m];
    }
    for (int j = tid; j < LL*DR; j += 256) {
        int t = j >> 5, dl = j & (DR-1);
        int off = sx[t]*DD + dbase + dl;
        se[j] = g_Eall[off];
        sa[j] = g_Aall[off];
    }

    const int g  = tid & 7;
    const int dl = tid >> 3;

    float mv[7];
    #pragma unroll
    for (int mi = 0; mi < 6; mi++)
        mv[mi] = Mv0[(g + NG*mi)*DD + dbase + dl];
    mv[6] = (g < 2) ? Mv0[(g + 48)*DD + dbase + dl] : 0.f;
    __syncthreads();

    float* outr = g_read + b*LL*DD + dbase + dl;

    for (int t = 0; t < LL; t++) {
        const float e  = se[t*DR + dl];
        const float a  = sa[t*DR + dl];
        const float* wt = sw + t*MM;
        float pr0 = 0.f, pr1 = 0.f;
        #pragma unroll
        for (int mi = 0; mi < 6; mi++) {
            float wm = wt[g + NG*mi];
            if (mi & 1) pr1 = fmaf(wm, mv[mi], pr1);
            else        pr0 = fmaf(wm, mv[mi], pr0);
            mv[mi] = fmaf(wm, fmaf(-e, mv[mi], a), mv[mi]);
        }
        if (g < 2) {
            float wm = wt[g + 48];
            pr1 = fmaf(wm, mv[6], pr1);
            mv[6] = fmaf(wm, fmaf(-e, mv[6], a), mv[6]);
        }
        float pr = pr0 + pr1;
        pr += __shfl_xor_sync(0xffffffffu, pr, 1);
        pr += __shfl_xor_sync(0xffffffffu, pr, 2);
        pr += __shfl_xor_sync(0xffffffffu, pr, 4);
        if (g == 0) outr[t*DD] = pr;
    }
}

// ============================================================
// Kernel C: output MLP, 16 positions / block, 4 per thread.
// ============================================================
__global__ __launch_bounds__(256) void output_kernel(
    const int*  __restrict__ cseqs, const int* __restrict__ shc,
    const float* __restrict__ Wf,   const float* __restrict__ Wp,
    const float* __restrict__ bp,   float* __restrict__ out)
{
    __shared__ float sW[DD*DD];        // Wf top half (read-part)
    __shared__ float rs[16][DD];
    __shared__ float spart[16][2];

    const int tid  = threadIdx.x;
    const int d    = tid & 63;
    const int pg   = tid >> 6;
    const int pbase = blockIdx.x * 16;

    #pragma unroll
    for (int j = tid; j < DD*DD; j += 256)
        sW[j] = Wf[j];
    #pragma unroll
    for (int j = tid; j < 16*DD; j += 256)
        rs[j >> 6][j & 63] = g_read[pbase*DD + j];
    __syncthreads();

    float acc[4];
    #pragma unroll
    for (int jj = 0; jj < 4; jj++) {
        int pos = pbase + pg*4 + jj;
        int bb = pos / LL, t = pos - bb*LL;
        int q = (t == 0) ? cseqs[bb*L1S] : shc[bb*L1S + t - 1];
        acc[jj] = g_Kf[q*DD + d];
    }

    #pragma unroll 4
    for (int i = 0; i < DD; i++) {
        float wv = sW[i*DD + d];
        acc[0] = fmaf(rs[pg*4 + 0][i], wv, acc[0]);
        acc[1] = fmaf(rs[pg*4 + 1][i], wv, acc[1]);
        acc[2] = fmaf(rs[pg*4 + 2][i], wv, acc[2]);
        acc[3] = fmaf(rs[pg*4 + 3][i], wv, acc[3]);
    }

    const float wp = Wp[d];
    #pragma unroll
    for (int jj = 0; jj < 4; jj++) {
        float p = tanhf(acc[jj]) * wp;
        #pragma unroll
        for (int o = 16; o > 0; o >>= 1)
            p += __shfl_xor_sync(0xffffffffu, p, o);
        if ((d & 31) == 0) spart[pg*4 + jj][d >> 5] = p;
    }
    __syncthreads();
    if (tid < 16) {
        float s = spart[tid][0] + spart[tid][1] + bp[0];
        out[pbase + tid] = 1.f / (1.f + __expf(-s));
    }
}

// ============================================================
extern "C" void kernel_launch(void* const* d_in, const int* in_sizes, int n_in,
                              void* d_out, int out_size)
{
    const int*   cseqs = (const int*)  d_in[0];
    const int*   rseqs = (const int*)  d_in[1];
    const int*   shc   = (const int*)  d_in[2];
    const int*   shr   = (const int*)  d_in[3];
    const float* kemb  = (const float*)d_in[4];
    const float* vemb  = (const float*)d_in[5];
    const float* Mk    = (const float*)d_in[6];
    const float* Mv0   = (const float*)d_in[7];
    const float* Wf    = (const float*)d_in[8];
    const float* bf    = (const float*)d_in[9];
    const float* We    = (const float*)d_in[10];
    const float* be    = (const float*)d_in[11];
    const float* Wa    = (const float*)d_in[12];
    const float* ba    = (const float*)d_in[13];
    const float* Wp    = (const float*)d_in[14];
    const float* bp    = (const float*)d_in[15];
    float* out = (float*)d_out;

    size_t vsm = (size_t)(3*DD*DD + DD*MM + 16*DD + 8*DD + 16) * sizeof(float);
    cudaFuncSetAttribute(vocab_kernel,
                         cudaFuncAttributeMaxDynamicSharedMemorySize, (int)vsm);
    vocab_kernel<<<2*NUMC/16, 256, vsm>>>(kemb, vemb, Mk, We, be, Wa, ba, Wf, bf);

    size_t ssm = (size_t)(LL*MM + 2*LL*DR) * sizeof(float) + 2*LL*sizeof(int);
    cudaFuncSetAttribute(scan_kernel,
                         cudaFuncAttributeMaxDynamicSharedMemorySize, (int)ssm);
    scan_kernel<<<BB*2, 256, ssm>>>(cseqs, rseqs, shc, shr, Mv0);

    output_kernel<<<BB*LL/16, 256>>>(cseqs, shc, Wf, Wp, bp, out);
}